// round 7
// baseline (speedup 1.0000x reference)
#include <cuda_runtime.h>
#include <cuda_fp16.h>
#include <math.h>
#include <stdint.h>

#define NW     4096
#define WLEN   16
#define GD     300
#define CE     50
#define CH     128
#define G4     512
#define CV     100
#define HID    512
#define FEAT   428

#define MW     32                 // words per CTA (MMA M)
#define THR    512                // 16 warps, each owns 32 gate columns
#define NBLK   (NW / MW)          // 128
#define KEXT   192                // 128 h + 50 emb + 1 bias + 13 pad
#define KATOMS (KEXT / 16)        // 12
#define ROWB   400                // smem row stride bytes (200 halves)
#define ABYTES (MW * ROWB)        // 12800

// ---- smem layout (total 231040; NO static __shared__ anywhere in mega) ----
#define SM_CI8   0                          // 32*16 u8 = 512
#define SM_WIDX  512                        // 32*4 = 128 (reused: is_last flag)
#define SM_A0    640                        // 12800 (reused: avg/r0s/r1s in final FC)
#define SM_A1    (SM_A0 + ABYTES)           // 13440
#define SM_B     (SM_A1 + ABYTES)           // 26240; 512*400 = 204800
#define SM_TOTAL (SM_B + G4 * ROWB)         // 231040

// ---- device scratch ----
__device__ __align__(16) __half g_embq[CV * 64];    // [emb(50) | 1 | 0pad] per char
__device__ float g_gsum[GD];
__device__ float g_hsum[CH];
__device__ int   g_ticket = 0;

// ---- helpers ----
__device__ __forceinline__ uint32_t smem_u32(const void* p) {
    uint32_t a;
    asm("{ .reg .u64 t; cvta.to.shared.u64 t, %1; cvt.u32.u64 %0, t; }" : "=r"(a) : "l"(p));
    return a;
}
__device__ __forceinline__ void ldsm4(uint32_t addr, uint32_t r[4]) {
    asm volatile("ldmatrix.sync.aligned.m8n8.x4.shared.b16 {%0,%1,%2,%3}, [%4];"
        : "=r"(r[0]), "=r"(r[1]), "=r"(r[2]), "=r"(r[3]) : "r"(addr));
}
__device__ __forceinline__ void mma16816(float d[4], const uint32_t a[4], const uint32_t b[2]) {
    asm volatile("mma.sync.aligned.m16n8k16.row.col.f32.f16.f16.f32 "
        "{%0,%1,%2,%3}, {%4,%5,%6,%7}, {%8,%9}, {%0,%1,%2,%3};"
        : "+f"(d[0]), "+f"(d[1]), "+f"(d[2]), "+f"(d[3])
        : "r"(a[0]), "r"(a[1]), "r"(a[2]), "r"(a[3]), "r"(b[0]), "r"(b[1]));
}
__device__ __forceinline__ float ex2a(float x) {
    float y; asm("ex2.approx.f32 %0, %1;" : "=f"(y) : "f"(x)); return y;
}
__device__ __forceinline__ float rcpa(float x) {
    float y; asm("rcp.approx.f32 %0, %1;" : "=f"(y) : "f"(x)); return y;
}
__device__ __forceinline__ float ldcv(const float* p) {
    float v; asm volatile("ld.global.cv.f32 %0, [%1];" : "=f"(v) : "l"(p)); return v;
}
#define NL2E (-1.4426950408889634f)

// gate-column permutation: warp w owns cols j = w*32 + c, c = a*8 + q*2 + e
//   gate g = 2*(a>>1) + e ; unit u = w*8 + (a&1)*4 + q

// ---------------------------------------------------------------------------
// Micro-prep: embq rows + zero accumulators. grid 101 x 64
// ---------------------------------------------------------------------------
__global__ void prep_small(const float* __restrict__ char_embed) {
    if (blockIdx.x < CV) {
        int cix = blockIdx.x, k = threadIdx.x;
        float v = (k < CE) ? char_embed[cix * CE + k] : (k == CE ? 1.f : 0.f);
        g_embq[cix * 64 + k] = __float2half(v);
    } else {
        for (int i = threadIdx.x; i < GD + CH; i += 64) {
            if (i < GD) g_gsum[i] = 0.f;
            else        g_hsum[i - GD] = 0.f;
        }
    }
}

// ---------------------------------------------------------------------------
// Mega kernel: per-CTA B build + glove gather + 16-step HMMA LSTM
// + last-CTA final FC. 128 CTAs x 512 threads.
// ---------------------------------------------------------------------------
__global__ void __launch_bounds__(THR, 1)
mega_kernel(const int* __restrict__ cidx, const int* __restrict__ widx,
            const float* __restrict__ glove,
            const float* __restrict__ W_hh, const float* __restrict__ W_ih,
            const float* __restrict__ b_ih, const float* __restrict__ b_hh,
            const float* __restrict__ fc1_w, const float* __restrict__ fc1_b,
            const float* __restrict__ fc2_w, const float* __restrict__ fc2_b,
            float* __restrict__ out) {
    extern __shared__ unsigned char sm[];
    uint32_t smb = smem_u32(sm);
    int tid = threadIdx.x;
    int w = tid >> 5, lane = tid & 31;
    int q = lane & 3, r = lane >> 2;
    const int wb = blockIdx.x * MW;

    // ---- char indices (packed u8) + word indices ----
    if (tid < MW * WLEN) sm[SM_CI8 + tid] = (unsigned char)cidx[wb * WLEN + tid];
    if (tid < MW) ((int*)(sm + SM_WIDX))[tid] = widx[wb + tid];

    // ---- zero A0 h-region ----
    {
        int row = tid >> 4, seg = tid & 15;   // 512 -> 32 rows x 16 segs (256B)
        *(uint4*)(sm + SM_A0 + row * ROWB + seg * 16) = make_uint4(0, 0, 0, 0);
    }

    // ---- build B_ext (permuted, fused) directly in smem: 24 segs/row ----
    for (int i = tid; i < G4 * 24; i += THR) {
        int j = i / 24, seg = i % 24;
        int ww = j >> 5, c = j & 31;
        int a = c >> 3, qq = (c >> 1) & 3, e = c & 1;
        int g = 2 * (a >> 1) + e;
        int u = ww * 8 + (a & 1) * 4 + qq;
        int row = g * CH + u;
        int k0 = seg * 8;
        __half2 h2v[4];
        if (seg < 16) {                       // W_hh fast path
            float4 v0 = *(const float4*)(W_hh + row * CH + k0);
            float4 v1 = *(const float4*)(W_hh + row * CH + k0 + 4);
            h2v[0] = __floats2half2_rn(v0.x, v0.y);
            h2v[1] = __floats2half2_rn(v0.z, v0.w);
            h2v[2] = __floats2half2_rn(v1.x, v1.y);
            h2v[3] = __floats2half2_rn(v1.z, v1.w);
        } else {                              // ext part: W_ih | bias | pad
            float v[8];
#pragma unroll
            for (int d = 0; d < 8; d++) {
                int k = k0 + d;
                float x;
                if (k < CH + CE)       x = W_ih[row * CE + (k - CH)];
                else if (k == CH + CE) x = b_ih[row] + b_hh[row];
                else                   x = 0.f;
                v[d] = x;
            }
#pragma unroll
            for (int d = 0; d < 4; d++) h2v[d] = __floats2half2_rn(v[2 * d], v[2 * d + 1]);
        }
        *(uint4*)(sm + SM_B + j * ROWB + seg * 16) = *(uint4*)h2v;
    }
    __syncthreads();

    // ---- stage emb for t=0 into A0 ----
    if (tid < 256) {
        int word = tid >> 3, seg = tid & 7;
        int ch = sm[SM_CI8 + word * WLEN];
        *(uint4*)(sm + SM_A0 + word * ROWB + 256 + seg * 16) =
            *(const uint4*)((const unsigned char*)g_embq + ch * 128 + seg * 16);
    }
    // ---- fused glove column-sum (DRAM otherwise idle) ----
    if (tid < GD) {
        const int* rows = (const int*)(sm + SM_WIDX);
        float s = 0.f;
#pragma unroll
        for (int ww = 0; ww < MW; ww++)
            s += glove[(long long)rows[ww] * GD + tid];
        atomicAdd(&g_gsum[tid], s);
    }
    __syncthreads();

    const uint32_t aoff = (uint32_t)((lane & 15) * ROWB + (lane >> 4) * 16);
    const uint32_t bBase = smb + SM_B + (w * 32 + (lane >> 4) * 8 + (lane & 7)) * ROWB
                         + ((lane >> 3) & 1) * 16;

    float cst[8], hs0 = 0.f, hs1 = 0.f;
#pragma unroll
    for (int i = 0; i < 8; i++) cst[i] = 0.f;

#pragma unroll 1
    for (int t = 0; t < WLEN; t++) {
        const uint32_t aCur = smb + SM_A0 + (t & 1) * ABYTES;
        const uint32_t aNxt = SM_A0 + ((t & 1) ^ 1) * ABYTES;
        uint32_t aBase = aCur + aoff;

        float acc[2][4][4];
#pragma unroll
        for (int m2 = 0; m2 < 2; m2++)
#pragma unroll
            for (int n = 0; n < 4; n++)
#pragma unroll
                for (int x = 0; x < 4; x++) acc[m2][n][x] = 0.f;

#pragma unroll
        for (int ka = 0; ka < KATOMS; ka++) {
            uint32_t af[2][4], bf[2][4];
            ldsm4(aBase + ka * 32, af[0]);
            ldsm4(aBase + 16 * ROWB + ka * 32, af[1]);
            ldsm4(bBase + ka * 32, bf[0]);
            ldsm4(bBase + 16 * ROWB + ka * 32, bf[1]);
#pragma unroll
            for (int m2 = 0; m2 < 2; m2++)
#pragma unroll
                for (int n = 0; n < 4; n++)
                    mma16816(acc[m2][n], af[m2], &bf[n >> 1][(n & 1) * 2]);
        }

        // epilogue compute (registers only) + stores into the OTHER A buffer
#pragma unroll
        for (int m2 = 0; m2 < 2; m2++)
#pragma unroll
            for (int h2 = 0; h2 < 2; h2++)
#pragma unroll
                for (int al = 0; al < 2; al++) {
                    float iv = acc[m2][al][h2 * 2];
                    float fv = acc[m2][al][h2 * 2 + 1];
                    float gv = acc[m2][al + 2][h2 * 2];
                    float ov = acc[m2][al + 2][h2 * 2 + 1];
                    int ci = (m2 * 2 + h2) * 2 + al;
                    float ei = ex2a(NL2E * iv);
                    float ef = ex2a(NL2E * fv);
                    float eg = ex2a(2.f * NL2E * gv);
                    float eo = ex2a(NL2E * ov);
                    float fg = rcpa(1.f + ef);
                    float ig = (1.f - eg) * rcpa((1.f + ei) * (1.f + eg));
                    float cn = fmaf(fg, cst[ci], ig);
                    cst[ci] = cn;
                    float ec = ex2a(2.f * NL2E * cn);
                    float hv = (1.f - ec) * rcpa((1.f + eo) * (1.f + ec));
                    int m = m2 * 16 + r + h2 * 8;
                    int u = w * 8 + al * 4 + q;
                    *(__half*)(sm + aNxt + m * ROWB + u * 2) = __float2half(hv);
                    if (t == WLEN - 1) { if (al == 0) hs0 += hv; else hs1 += hv; }
                }

        if (t < WLEN - 1 && tid < 256) {   // stage emb for t+1 into A[next]
            int word = tid >> 3, seg = tid & 7;
            int ch = sm[SM_CI8 + word * WLEN + t + 1];
            *(uint4*)(sm + aNxt + word * ROWB + 256 + seg * 16) =
                *(const uint4*)((const unsigned char*)g_embq + ch * 128 + seg * 16);
        }
        __syncthreads();   // single barrier: covers RAW (h,emb) and WAR (buffers)
    }

    // ---- reduce final h over the CTA's 32 words -> g_hsum ----
#pragma unroll
    for (int off = 4; off < 32; off <<= 1) {
        hs0 += __shfl_xor_sync(0xffffffffu, hs0, off);
        hs1 += __shfl_xor_sync(0xffffffffu, hs1, off);
    }
    if (lane < 4) {
        atomicAdd(&g_hsum[w * 8 + lane], hs0);
        atomicAdd(&g_hsum[w * 8 + 4 + lane], hs1);
    }

    // ---- last-CTA final FC (ticket); ALL shared storage reuses dynamic smem ----
    __threadfence();
    int* is_last = (int*)(sm + SM_WIDX);          // widx dead now
    if (tid == 0) {
        int old = atomicAdd(&g_ticket, 1);
        *is_last = (old == NBLK - 1);
    }
    __syncthreads();
    if (!*is_last) return;

    float* avg = (float*)(sm + SM_A0);            // A buffers dead now
    float* r0s = (float*)(sm + SM_A0 + FEAT * 4);
    float* r1s = r0s + 16;
    if (tid < GD) avg[tid] = ldcv(&g_gsum[tid]) * (1.f / NW);
    else if (tid < FEAT) avg[tid] = ldcv(&g_hsum[tid - GD]) * (1.f / NW);
    __syncthreads();

    float h = fc1_b[tid];
    const float* wv = fc1_w + tid * FEAT;
#pragma unroll 4
    for (int k = 0; k < FEAT; k++) h = fmaf(wv[k], avg[k], h);
    h = fmaxf(h, 0.f);

    float p0 = fc2_w[tid] * h;
    float p1 = fc2_w[HID + tid] * h;
#pragma unroll
    for (int off = 16; off; off >>= 1) {
        p0 += __shfl_down_sync(0xffffffffu, p0, off);
        p1 += __shfl_down_sync(0xffffffffu, p1, off);
    }
    if (lane == 0) { r0s[w] = p0; r1s[w] = p1; }
    __syncthreads();
    if (tid == 0) {
        float a = 0.f, b = 0.f;
#pragma unroll
        for (int i = 0; i < 16; i++) { a += r0s[i]; b += r1s[i]; }
        out[0] = a + fc2_b[0];
        out[1] = b + fc2_b[1];
        g_ticket = 0;   // reset for next graph replay (deterministic)
    }
}

// ---------------------------------------------------------------------------
extern "C" void kernel_launch(void* const* d_in, const int* in_sizes, int n_in,
                              void* d_out, int out_size) {
    const int*   widx  = (const int*)d_in[0];
    const int*   cidx  = (const int*)d_in[1];
    const float* glove = (const float*)d_in[2];
    const float* cemb  = (const float*)d_in[3];
    const float* W_ih  = (const float*)d_in[4];
    const float* W_hh  = (const float*)d_in[5];
    const float* b_ih  = (const float*)d_in[6];
    const float* b_hh  = (const float*)d_in[7];
    const float* fc1_w = (const float*)d_in[8];
    const float* fc1_b = (const float*)d_in[9];
    const float* fc2_w = (const float*)d_in[10];
    const float* fc2_b = (const float*)d_in[11];
    float* out = (float*)d_out;

    cudaFuncSetAttribute(mega_kernel,
                         cudaFuncAttributeMaxDynamicSharedMemorySize, SM_TOTAL);

    prep_small<<<CV + 1, 64>>>(cemb);
    mega_kernel<<<NBLK, THR, SM_TOTAL>>>(cidx, widx, glove,
                                         W_hh, W_ih, b_ih, b_hh,
                                         fc1_w, fc1_b, fc2_w, fc2_b, out);
}

// round 8
// speedup vs baseline: 1.0885x; 1.0885x over previous
#include <cuda_runtime.h>
#include <cuda_fp16.h>
#include <math.h>
#include <stdint.h>

#define NW     4096
#define WLEN   16
#define GD     300
#define CE     50
#define CH     128
#define G4     512
#define CV     100
#define HID    512
#define FEAT   428

#define MW     32                 // words per CTA (MMA M)
#define THR    512                // 16 warps, each owns 32 gate columns
#define NBLK   (NW / MW)          // 128
#define KEXT   192                // 128 h + 50 emb + 1 bias + 13 pad
#define KATOMS (KEXT / 16)        // 12
#define ROWB   400                // smem row stride bytes (200 halves)
#define ABYTES (MW * ROWB)        // 12800

// ---- smem layout (total 231040; NO static __shared__ in mega) ----
#define SM_CI8   0                          // 32*16 u8 = 512
#define SM_WIDX  512                        // 32*4 = 128 (reused: is_last flag)
#define SM_A0    640                        // 12800 (reused: avg/r0s/r1s in final FC)
#define SM_A1    (SM_A0 + ABYTES)           // 13440
#define SM_B     (SM_A1 + ABYTES)           // 26240; 512*400 = 204800
#define SM_TOTAL (SM_B + G4 * ROWB)         // 231040

// ---- device scratch ----
__device__ __align__(16) __half g_Bext[G4 * KEXT];  // permuted fused weights (built once)
__device__ __align__(16) __half g_embq[CV * 64];    // [emb(50) | 1 | 0pad] per char
__device__ float g_gsum[GD];
__device__ float g_hsum[CH];
__device__ int   g_ticket = 0;

// ---- helpers ----
__device__ __forceinline__ uint32_t smem_u32(const void* p) {
    uint32_t a;
    asm("{ .reg .u64 t; cvta.to.shared.u64 t, %1; cvt.u32.u64 %0, t; }" : "=r"(a) : "l"(p));
    return a;
}
__device__ __forceinline__ void ldsm4(uint32_t addr, uint32_t r[4]) {
    asm volatile("ldmatrix.sync.aligned.m8n8.x4.shared.b16 {%0,%1,%2,%3}, [%4];"
        : "=r"(r[0]), "=r"(r[1]), "=r"(r[2]), "=r"(r[3]) : "r"(addr));
}
__device__ __forceinline__ void mma16816(float d[4], const uint32_t a[4], const uint32_t b[2]) {
    asm volatile("mma.sync.aligned.m16n8k16.row.col.f32.f16.f16.f32 "
        "{%0,%1,%2,%3}, {%4,%5,%6,%7}, {%8,%9}, {%0,%1,%2,%3};"
        : "+f"(d[0]), "+f"(d[1]), "+f"(d[2]), "+f"(d[3])
        : "r"(a[0]), "r"(a[1]), "r"(a[2]), "r"(a[3]), "r"(b[0]), "r"(b[1]));
}
__device__ __forceinline__ float ex2a(float x) {
    float y; asm("ex2.approx.f32 %0, %1;" : "=f"(y) : "f"(x)); return y;
}
__device__ __forceinline__ float rcpa(float x) {
    float y; asm("rcp.approx.f32 %0, %1;" : "=f"(y) : "f"(x)); return y;
}
__device__ __forceinline__ float ldcv(const float* p) {
    float v; asm volatile("ld.global.cv.f32 %0, [%1];" : "=f"(v) : "l"(p)); return v;
}
#define NL2E (-1.4426950408889634f)

// gate-column permutation: warp w owns cols j = w*32 + c, c = a*8 + q*2 + e
//   gate g = 2*(a>>1) + e ; unit u = w*8 + (a&1)*4 + q

// ---------------------------------------------------------------------------
// Prep (round-5 proven): blocks 0..511 build g_Bext; 512..611 embq + zeros.
// grid 612 x 96
// ---------------------------------------------------------------------------
__global__ void prep_all(const float* __restrict__ W_hh, const float* __restrict__ W_ih,
                         const float* __restrict__ b_ih, const float* __restrict__ b_hh,
                         const float* __restrict__ char_embed) {
    if (blockIdx.x < G4) {
        int j = blockIdx.x;
        int w = j >> 5, c = j & 31;
        int a = c >> 3, q = (c >> 1) & 3, e = c & 1;
        int g = 2 * (a >> 1) + e;
        int u = w * 8 + (a & 1) * 4 + q;
        int row = g * CH + u;
        int k0 = threadIdx.x * 2;
        float v[2];
#pragma unroll
        for (int d = 0; d < 2; d++) {
            int k = k0 + d;
            float x;
            if (k < CH)            x = W_hh[row * CH + k];
            else if (k < CH + CE)  x = W_ih[row * CE + (k - CH)];
            else if (k == CH + CE) x = b_ih[row] + b_hh[row];
            else                   x = 0.f;
            v[d] = x;
        }
        *(__half2*)(g_Bext + j * KEXT + k0) = __floats2half2_rn(v[0], v[1]);
    } else {
        int cix = blockIdx.x - G4;
        int k = threadIdx.x;
        if (k < 64) {
            float v = (k < CE) ? char_embed[cix * CE + k] : (k == CE ? 1.f : 0.f);
            g_embq[cix * 64 + k] = __float2half(v);
        }
        int z = cix * 96 + threadIdx.x;
        if (z < GD) g_gsum[z] = 0.f;
        if (z < CH) g_hsum[z] = 0.f;
    }
}

// ---------------------------------------------------------------------------
// Mega kernel: B stream-in + glove gather + 16-step HMMA LSTM (1 barrier/step)
// + last-CTA final FC. 128 CTAs x 512 threads.
// ---------------------------------------------------------------------------
__global__ void __launch_bounds__(THR, 1)
mega_kernel(const int* __restrict__ cidx, const int* __restrict__ widx,
            const float* __restrict__ glove,
            const float* __restrict__ fc1_w, const float* __restrict__ fc1_b,
            const float* __restrict__ fc2_w, const float* __restrict__ fc2_b,
            float* __restrict__ out) {
    extern __shared__ unsigned char sm[];
    uint32_t smb = smem_u32(sm);
    int tid = threadIdx.x;
    int w = tid >> 5, lane = tid & 31;
    int q = lane & 3, r = lane >> 2;
    const int wb = blockIdx.x * MW;

    // ---- char indices (packed u8) + word indices ----
    if (tid < MW * WLEN) sm[SM_CI8 + tid] = (unsigned char)cidx[wb * WLEN + tid];
    if (tid < MW) ((int*)(sm + SM_WIDX))[tid] = widx[wb + tid];

    // ---- zero A0 h-region ----
    {
        int row = tid >> 4, seg = tid & 15;   // 32 rows x 16 segs (256B each row)
        *(uint4*)(sm + SM_A0 + row * ROWB + seg * 16) = make_uint4(0, 0, 0, 0);
    }

    // ---- stream prebuilt B_ext from global (L2-resident, shared by all CTAs) ----
    for (int i = tid; i < G4 * 24; i += THR) {     // 24 uint4 per 192-half row
        int row = i / 24, s = i % 24;
        *(uint4*)(sm + SM_B + row * ROWB + s * 16) =
            *(const uint4*)((const unsigned char*)g_Bext + i * 16);
    }
    __syncthreads();

    // ---- stage emb for t=0 into A0 ----
    if (tid < 256) {
        int word = tid >> 3, seg = tid & 7;
        int ch = sm[SM_CI8 + word * WLEN];
        *(uint4*)(sm + SM_A0 + word * ROWB + 256 + seg * 16) =
            *(const uint4*)((const unsigned char*)g_embq + ch * 128 + seg * 16);
    }
    // ---- fused glove column-sum (DRAM otherwise idle) ----
    if (tid < GD) {
        const int* rows = (const int*)(sm + SM_WIDX);
        float s = 0.f;
#pragma unroll
        for (int ww = 0; ww < MW; ww++)
            s += glove[(long long)rows[ww] * GD + tid];
        atomicAdd(&g_gsum[tid], s);
    }
    __syncthreads();

    const uint32_t aoff = (uint32_t)((lane & 15) * ROWB + (lane >> 4) * 16);
    const uint32_t bBase = smb + SM_B + (w * 32 + (lane >> 4) * 8 + (lane & 7)) * ROWB
                         + ((lane >> 3) & 1) * 16;

    float cst[8], hs0 = 0.f, hs1 = 0.f;
#pragma unroll
    for (int i = 0; i < 8; i++) cst[i] = 0.f;

#pragma unroll 1
    for (int t = 0; t < WLEN; t++) {
        const uint32_t aCur = smb + SM_A0 + (t & 1) * ABYTES;
        const uint32_t aNxt = SM_A0 + ((t & 1) ^ 1) * ABYTES;
        uint32_t aBase = aCur + aoff;

        float acc[2][4][4];
#pragma unroll
        for (int m2 = 0; m2 < 2; m2++)
#pragma unroll
            for (int n = 0; n < 4; n++)
#pragma unroll
                for (int x = 0; x < 4; x++) acc[m2][n][x] = 0.f;

#pragma unroll
        for (int ka = 0; ka < KATOMS; ka++) {
            uint32_t af[2][4], bf[2][4];
            ldsm4(aBase + ka * 32, af[0]);
            ldsm4(aBase + 16 * ROWB + ka * 32, af[1]);
            ldsm4(bBase + ka * 32, bf[0]);
            ldsm4(bBase + 16 * ROWB + ka * 32, bf[1]);
#pragma unroll
            for (int m2 = 0; m2 < 2; m2++)
#pragma unroll
                for (int n = 0; n < 4; n++)
                    mma16816(acc[m2][n], af[m2], &bf[n >> 1][(n & 1) * 2]);
        }

        // epilogue compute (registers only) + stores into the OTHER A buffer
#pragma unroll
        for (int m2 = 0; m2 < 2; m2++)
#pragma unroll
            for (int h2 = 0; h2 < 2; h2++)
#pragma unroll
                for (int al = 0; al < 2; al++) {
                    float iv = acc[m2][al][h2 * 2];
                    float fv = acc[m2][al][h2 * 2 + 1];
                    float gv = acc[m2][al + 2][h2 * 2];
                    float ov = acc[m2][al + 2][h2 * 2 + 1];
                    int ci = (m2 * 2 + h2) * 2 + al;
                    float ei = ex2a(NL2E * iv);
                    float ef = ex2a(NL2E * fv);
                    float eg = ex2a(2.f * NL2E * gv);
                    float eo = ex2a(NL2E * ov);
                    float fg = rcpa(1.f + ef);
                    float ig = (1.f - eg) * rcpa((1.f + ei) * (1.f + eg));
                    float cn = fmaf(fg, cst[ci], ig);
                    cst[ci] = cn;
                    float ec = ex2a(2.f * NL2E * cn);
                    float hv = (1.f - ec) * rcpa((1.f + eo) * (1.f + ec));
                    int m = m2 * 16 + r + h2 * 8;
                    int u = w * 8 + al * 4 + q;
                    *(__half*)(sm + aNxt + m * ROWB + u * 2) = __float2half(hv);
                    if (t == WLEN - 1) { if (al == 0) hs0 += hv; else hs1 += hv; }
                }

        if (t < WLEN - 1 && tid < 256) {   // stage emb for t+1 into A[next]
            int word = tid >> 3, seg = tid & 7;
            int ch = sm[SM_CI8 + word * WLEN + t + 1];
            *(uint4*)(sm + aNxt + word * ROWB + 256 + seg * 16) =
                *(const uint4*)((const unsigned char*)g_embq + ch * 128 + seg * 16);
        }
        __syncthreads();   // single barrier: covers RAW (h,emb) and WAR (buffers)
    }

    // ---- reduce final h over the CTA's 32 words -> g_hsum ----
#pragma unroll
    for (int off = 4; off < 32; off <<= 1) {
        hs0 += __shfl_xor_sync(0xffffffffu, hs0, off);
        hs1 += __shfl_xor_sync(0xffffffffu, hs1, off);
    }
    if (lane < 4) {
        atomicAdd(&g_hsum[w * 8 + lane], hs0);
        atomicAdd(&g_hsum[w * 8 + 4 + lane], hs1);
    }

    // ---- last-CTA final FC (ticket); all shared storage reuses dynamic smem ----
    __threadfence();
    int* is_last = (int*)(sm + SM_WIDX);          // widx dead now
    if (tid == 0) {
        int old = atomicAdd(&g_ticket, 1);
        *is_last = (old == NBLK - 1);
    }
    __syncthreads();
    if (!*is_last) return;

    float* avg = (float*)(sm + SM_A0);            // A buffers dead now
    float* r0s = (float*)(sm + SM_A0 + FEAT * 4);
    float* r1s = r0s + 16;
    if (tid < GD) avg[tid] = ldcv(&g_gsum[tid]) * (1.f / NW);
    else if (tid < FEAT) avg[tid] = ldcv(&g_hsum[tid - GD]) * (1.f / NW);
    __syncthreads();

    float h = fc1_b[tid];
    const float* wv = fc1_w + tid * FEAT;
#pragma unroll 4
    for (int k = 0; k < FEAT; k++) h = fmaf(wv[k], avg[k], h);
    h = fmaxf(h, 0.f);

    float p0 = fc2_w[tid] * h;
    float p1 = fc2_w[HID + tid] * h;
#pragma unroll
    for (int off = 16; off; off >>= 1) {
        p0 += __shfl_down_sync(0xffffffffu, p0, off);
        p1 += __shfl_down_sync(0xffffffffu, p1, off);
    }
    if (lane == 0) { r0s[w] = p0; r1s[w] = p1; }
    __syncthreads();
    if (tid == 0) {
        float a = 0.f, b = 0.f;
#pragma unroll
        for (int i = 0; i < 16; i++) { a += r0s[i]; b += r1s[i]; }
        out[0] = a + fc2_b[0];
        out[1] = b + fc2_b[1];
        g_ticket = 0;   // reset for next graph replay (deterministic)
    }
}

// ---------------------------------------------------------------------------
extern "C" void kernel_launch(void* const* d_in, const int* in_sizes, int n_in,
                              void* d_out, int out_size) {
    const int*   widx  = (const int*)d_in[0];
    const int*   cidx  = (const int*)d_in[1];
    const float* glove = (const float*)d_in[2];
    const float* cemb  = (const float*)d_in[3];
    const float* W_ih  = (const float*)d_in[4];
    const float* W_hh  = (const float*)d_in[5];
    const float* b_ih  = (const float*)d_in[6];
    const float* b_hh  = (const float*)d_in[7];
    const float* fc1_w = (const float*)d_in[8];
    const float* fc1_b = (const float*)d_in[9];
    const float* fc2_w = (const float*)d_in[10];
    const float* fc2_b = (const float*)d_in[11];
    float* out = (float*)d_out;

    cudaFuncSetAttribute(mega_kernel,
                         cudaFuncAttributeMaxDynamicSharedMemorySize, SM_TOTAL);

    prep_all<<<G4 + CV, 96>>>(W_hh, W_ih, b_ih, b_hh, cemb);
    mega_kernel<<<NBLK, THR, SM_TOTAL>>>(cidx, widx, glove,
                                         fc1_w, fc1_b, fc2_w, fc2_b, out);
}

// round 9
// speedup vs baseline: 2.0751x; 1.9063x over previous
#include <cuda_runtime.h>
#include <cuda_fp16.h>
#include <math.h>
#include <stdint.h>

#define NW     4096
#define WLEN   16
#define GD     300
#define CE     50
#define CH     128
#define G4     512
#define CV     100
#define HID    512
#define FEAT   428

#define MW     32                 // words per CTA (MMA M)
#define THR    512                // 16 warps, each owns 32 gate columns
#define NBLK   (NW / MW)          // 128
#define KEXT   192                // 128 h + 50 emb + 1 bias + 13 pad
#define KATOMS (KEXT / 16)        // 12
#define ROWB   400                // smem row stride bytes (200 halves)

// ---- smem layout (round-5 proven) ----
#define SM_CI    0                          // 32*16*4 = 2048
#define SM_WIDX  2048                       // 32*4 = 128
#define SM_A     2176                       // 32*400 = 12800
#define SM_B     (SM_A + MW * ROWB)         // 14976; 512*400 = 204800
#define SM_TOTAL (SM_B + G4 * ROWB)         // 219776

// ---- device scratch ----
__device__ __align__(16) __half g_Bext[G4 * KEXT];  // permuted fused weights
__device__ __align__(16) __half g_embq[CV * 64];    // [emb(50) | 1 | 0pad] per char
__device__ float g_gsum[GD];
__device__ float g_hsum[CH];
__device__ float g_out2[2];
__device__ int   g_t2 = 0;

// ---- helpers ----
__device__ __forceinline__ uint32_t smem_u32(const void* p) {
    uint32_t a;
    asm("{ .reg .u64 t; cvta.to.shared.u64 t, %1; cvt.u32.u64 %0, t; }" : "=r"(a) : "l"(p));
    return a;
}
__device__ __forceinline__ void ldsm4(uint32_t addr, uint32_t r[4]) {
    asm volatile("ldmatrix.sync.aligned.m8n8.x4.shared.b16 {%0,%1,%2,%3}, [%4];"
        : "=r"(r[0]), "=r"(r[1]), "=r"(r[2]), "=r"(r[3]) : "r"(addr));
}
__device__ __forceinline__ void mma16816(float d[4], const uint32_t a[4], const uint32_t b[2]) {
    asm volatile("mma.sync.aligned.m16n8k16.row.col.f32.f16.f16.f32 "
        "{%0,%1,%2,%3}, {%4,%5,%6,%7}, {%8,%9}, {%0,%1,%2,%3};"
        : "+f"(d[0]), "+f"(d[1]), "+f"(d[2]), "+f"(d[3])
        : "r"(a[0]), "r"(a[1]), "r"(a[2]), "r"(a[3]), "r"(b[0]), "r"(b[1]));
}
__device__ __forceinline__ float ex2a(float x) {
    float y; asm("ex2.approx.f32 %0, %1;" : "=f"(y) : "f"(x)); return y;
}
__device__ __forceinline__ float rcpa(float x) {
    float y; asm("rcp.approx.f32 %0, %1;" : "=f"(y) : "f"(x)); return y;
}
__device__ __forceinline__ float ldcv(const float* p) {
    float v; asm volatile("ld.global.cv.f32 %0, [%1];" : "=f"(v) : "l"(p)); return v;
}
#define NL2E (-1.4426950408889634f)

// gate-column permutation: warp w owns cols j = w*32 + c, c = a*8 + q*2 + e
//   gate g = 2*(a>>1) + e ; unit u = w*8 + (a&1)*4 + q

// ---------------------------------------------------------------------------
// Prep (round-5 proven): blocks 0..511 build g_Bext; 512..611 embq + zeros.
// grid 612 x 96
// ---------------------------------------------------------------------------
__global__ void prep_all(const float* __restrict__ W_hh, const float* __restrict__ W_ih,
                         const float* __restrict__ b_ih, const float* __restrict__ b_hh,
                         const float* __restrict__ char_embed) {
    if (blockIdx.x < G4) {
        int j = blockIdx.x;
        int w = j >> 5, c = j & 31;
        int a = c >> 3, q = (c >> 1) & 3, e = c & 1;
        int g = 2 * (a >> 1) + e;
        int u = w * 8 + (a & 1) * 4 + q;
        int row = g * CH + u;
        int k0 = threadIdx.x * 2;
        float v[2];
#pragma unroll
        for (int d = 0; d < 2; d++) {
            int k = k0 + d;
            float x;
            if (k < CH)            x = W_hh[row * CH + k];
            else if (k < CH + CE)  x = W_ih[row * CE + (k - CH)];
            else if (k == CH + CE) x = b_ih[row] + b_hh[row];
            else                   x = 0.f;
            v[d] = x;
        }
        *(__half2*)(g_Bext + j * KEXT + k0) = __floats2half2_rn(v[0], v[1]);
    } else {
        int cix = blockIdx.x - G4;
        int k = threadIdx.x;
        if (k < 64) {
            float v = (k < CE) ? char_embed[cix * CE + k] : (k == CE ? 1.f : 0.f);
            g_embq[cix * 64 + k] = __float2half(v);
        }
        int z = cix * 96 + threadIdx.x;
        if (z < GD) g_gsum[z] = 0.f;
        if (z < CH) g_hsum[z] = 0.f;
        if (blockIdx.x == G4 && threadIdx.x == 0) {
            g_out2[0] = 0.f; g_out2[1] = 0.f; g_t2 = 0;
        }
    }
}

// ---------------------------------------------------------------------------
// LSTM via mma.sync + fused glove gather (EXACT round-5 kernel, 113.1us config)
// 128 CTAs x 512 thr; M=32 words, N=512 gates, K=192. B_ext smem-resident.
// ---------------------------------------------------------------------------
__global__ void __launch_bounds__(THR, 1) lstm_mma_kernel(const int* __restrict__ cidx,
                                                          const int* __restrict__ widx,
                                                          const float* __restrict__ glove) {
    extern __shared__ unsigned char sm[];
    uint32_t smb = smem_u32(sm);
    int tid = threadIdx.x;
    int w = tid >> 5, lane = tid & 31;
    int q = lane & 3, r = lane >> 2;

    const int wb = blockIdx.x * MW;
    for (int i = tid; i < MW * WLEN; i += THR)
        ((int*)(sm + SM_CI))[i] = cidx[wb * WLEN + i];
    if (tid < MW) ((int*)(sm + SM_WIDX))[tid] = widx[wb + tid];
    for (int i = tid; i < MW * ROWB / 16; i += THR)
        ((uint4*)(sm + SM_A))[i] = make_uint4(0, 0, 0, 0);
    for (int i = tid; i < G4 * 24; i += THR) {        // 24 uint4 per 192-half row
        int row = i / 24, s = i % 24;
        *(uint4*)(sm + SM_B + row * ROWB + s * 16) =
            *(const uint4*)((const unsigned char*)g_Bext + i * 16);
    }
    __syncthreads();

    // stage emb for t=0
    if (tid < 256) {
        int word = tid >> 3, seg = tid & 7;
        int ch = ((const int*)(sm + SM_CI))[word * WLEN];
        *(uint4*)(sm + SM_A + word * ROWB + 256 + seg * 16) =
            *(const uint4*)((const unsigned char*)g_embq + ch * 128 + seg * 16);
    }
    // fused glove column-sum for this CTA's 32 words
    if (tid < GD) {
        const int* rows = (const int*)(sm + SM_WIDX);
        float s = 0.f;
#pragma unroll
        for (int ww = 0; ww < MW; ww++)
            s += glove[(long long)rows[ww] * GD + tid];
        atomicAdd(&g_gsum[tid], s);
    }
    __syncthreads();

    // ldmatrix base addresses (loop-invariant)
    uint32_t aBase = smb + SM_A + (lane & 15) * ROWB + (lane >> 4) * 16;
    uint32_t bBase = smb + SM_B + (w * 32 + (lane >> 4) * 8 + (lane & 7)) * ROWB
                   + ((lane >> 3) & 1) * 16;

    float cst[8], hs0 = 0.f, hs1 = 0.f;
#pragma unroll
    for (int i = 0; i < 8; i++) cst[i] = 0.f;

#pragma unroll 1
    for (int t = 0; t < WLEN; t++) {
        float acc[2][4][4];
#pragma unroll
        for (int m2 = 0; m2 < 2; m2++)
#pragma unroll
            for (int n = 0; n < 4; n++)
#pragma unroll
                for (int x = 0; x < 4; x++) acc[m2][n][x] = 0.f;

#pragma unroll
        for (int ka = 0; ka < KATOMS; ka++) {
            uint32_t af[2][4], bf[2][4];
            ldsm4(aBase + ka * 32, af[0]);
            ldsm4(aBase + 16 * ROWB + ka * 32, af[1]);
            ldsm4(bBase + ka * 32, bf[0]);
            ldsm4(bBase + 16 * ROWB + ka * 32, bf[1]);
#pragma unroll
            for (int m2 = 0; m2 < 2; m2++)
#pragma unroll
                for (int n = 0; n < 4; n++)
                    mma16816(acc[m2][n], af[m2], &bf[n >> 1][(n & 1) * 2]);
        }

        // epilogue compute (registers only) — overlaps across warps
        float hreg[8];
#pragma unroll
        for (int m2 = 0; m2 < 2; m2++)
#pragma unroll
            for (int h2 = 0; h2 < 2; h2++)
#pragma unroll
                for (int al = 0; al < 2; al++) {
                    float iv = acc[m2][al][h2 * 2];
                    float fv = acc[m2][al][h2 * 2 + 1];
                    float gv = acc[m2][al + 2][h2 * 2];
                    float ov = acc[m2][al + 2][h2 * 2 + 1];
                    int ci = (m2 * 2 + h2) * 2 + al;
                    float ei = ex2a(NL2E * iv);
                    float ef = ex2a(NL2E * fv);
                    float eg = ex2a(2.f * NL2E * gv);
                    float eo = ex2a(NL2E * ov);
                    float fg = rcpa(1.f + ef);
                    float ig = (1.f - eg) * rcpa((1.f + ei) * (1.f + eg));
                    float cn = fmaf(fg, cst[ci], ig);
                    cst[ci] = cn;
                    float ec = ex2a(2.f * NL2E * cn);
                    hreg[ci] = (1.f - ec) * rcpa((1.f + eo) * (1.f + ec));
                }
        __syncthreads();   // all ldsm A-reads done before h/emb overwrite

#pragma unroll
        for (int m2 = 0; m2 < 2; m2++)
#pragma unroll
            for (int h2 = 0; h2 < 2; h2++)
#pragma unroll
                for (int al = 0; al < 2; al++) {
                    int ci = (m2 * 2 + h2) * 2 + al;
                    int m = m2 * 16 + r + h2 * 8;
                    int u = w * 8 + al * 4 + q;
                    *(__half*)(sm + SM_A + m * ROWB + u * 2) = __float2half(hreg[ci]);
                }
        if (t == WLEN - 1) {
#pragma unroll
            for (int ci = 0; ci < 8; ci++) {
                if ((ci & 1) == 0) hs0 += hreg[ci]; else hs1 += hreg[ci];
            }
        } else if (tid < 256) {   // stage emb for t+1
            int word = tid >> 3, seg = tid & 7;
            int ch = ((const int*)(sm + SM_CI))[word * WLEN + t + 1];
            *(uint4*)(sm + SM_A + word * ROWB + 256 + seg * 16) =
                *(const uint4*)((const unsigned char*)g_embq + ch * 128 + seg * 16);
        }
        __syncthreads();   // h + emb visible for next step
    }

    // reduce final h over the CTA's 32 words -> g_hsum
#pragma unroll
    for (int off = 4; off < 32; off <<= 1) {
        hs0 += __shfl_xor_sync(0xffffffffu, hs0, off);
        hs1 += __shfl_xor_sync(0xffffffffu, hs1, off);
    }
    if (lane < 4) {
        atomicAdd(&g_hsum[w * 8 + lane], hs0);
        atomicAdd(&g_hsum[w * 8 + 4 + lane], hs1);
    }
}

// ---------------------------------------------------------------------------
// Final: avg -> fc1 + relu -> fc2, parallelized over 8 CTAs.
// 8 threads per hidden unit, coalesced fc1_w reads; fc2 via atomic partials;
// ticketed last CTA writes out. grid 8 x 512
// ---------------------------------------------------------------------------
__global__ void final_kernel(const float* __restrict__ fc1_w,
                             const float* __restrict__ fc1_b,
                             const float* __restrict__ fc2_w,
                             const float* __restrict__ fc2_b,
                             float* __restrict__ out) {
    __shared__ float avg[FEAT];
    int tid = threadIdx.x;
    int lane = tid & 31;
    int e = tid & 7;                     // chunk within unit
    int j = blockIdx.x * 64 + (tid >> 3);  // hidden unit

    if (tid < GD) avg[tid] = g_gsum[tid] * (1.f / NW);
    else if (tid < FEAT) avg[tid] = g_hsum[tid - GD] * (1.f / NW);
    __syncthreads();

    // partial dot over chunk [e*54, e*54+54) ∩ [0,428)
    int k0 = e * 54;
    int k1 = (k0 + 54 < FEAT) ? k0 + 54 : FEAT;
    const float* wrow = fc1_w + (long long)j * FEAT;
    float p = 0.f;
#pragma unroll 6
    for (int k = k0; k < k1; k++) p = fmaf(wrow[k], avg[k], p);
    // reduce the 8-lane group
    p += __shfl_down_sync(0xffffffffu, p, 4, 8);
    p += __shfl_down_sync(0xffffffffu, p, 2, 8);
    p += __shfl_down_sync(0xffffffffu, p, 1, 8);

    float q0 = 0.f, q1 = 0.f;
    if (e == 0) {
        float h = fmaxf(p + fc1_b[j], 0.f);
        q0 = fc2_w[j] * h;
        q1 = fc2_w[HID + j] * h;
    }
    // warp reduce (4 units per warp at lanes 0,8,16,24)
#pragma unroll
    for (int off = 16; off >= 8; off >>= 1) {
        q0 += __shfl_down_sync(0xffffffffu, q0, off);
        q1 += __shfl_down_sync(0xffffffffu, q1, off);
    }
    if (lane == 0) {
        atomicAdd(&g_out2[0], q0);
        atomicAdd(&g_out2[1], q1);
    }
    __threadfence();
    __syncthreads();
    if (tid == 0) {
        int old = atomicAdd(&g_t2, 1);
        if (old == 7) {
            out[0] = ldcv(&g_out2[0]) + fc2_b[0];
            out[1] = ldcv(&g_out2[1]) + fc2_b[1];
        }
    }
}

// ---------------------------------------------------------------------------
extern "C" void kernel_launch(void* const* d_in, const int* in_sizes, int n_in,
                              void* d_out, int out_size) {
    const int*   widx  = (const int*)d_in[0];
    const int*   cidx  = (const int*)d_in[1];
    const float* glove = (const float*)d_in[2];
    const float* cemb  = (const float*)d_in[3];
    const float* W_ih  = (const float*)d_in[4];
    const float* W_hh  = (const float*)d_in[5];
    const float* b_ih  = (const float*)d_in[6];
    const float* b_hh  = (const float*)d_in[7];
    const float* fc1_w = (const float*)d_in[8];
    const float* fc1_b = (const float*)d_in[9];
    const float* fc2_w = (const float*)d_in[10];
    const float* fc2_b = (const float*)d_in[11];
    float* out = (float*)d_out;

    cudaFuncSetAttribute(lstm_mma_kernel,
                         cudaFuncAttributeMaxDynamicSharedMemorySize, SM_TOTAL);

    prep_all<<<G4 + CV, 96>>>(W_hh, W_ih, b_ih, b_hh, cemb);
    lstm_mma_kernel<<<NBLK, THR, SM_TOTAL>>>(cidx, widx, glove);
    final_kernel<<<8, 512>>>(fc1_w, fc1_b, fc2_w, fc2_b, out);
}

// round 10
// speedup vs baseline: 2.2098x; 1.0649x over previous
#include <cuda_runtime.h>
#include <cuda_fp16.h>
#include <math.h>
#include <stdint.h>

#define NW     4096
#define WLEN   16
#define GD     300
#define CE     50
#define CH     128
#define G4     512
#define CV     100
#define HID    512
#define FEAT   428

#define MW     32                 // words per CTA (MMA M)
#define THR    512                // 16 warps, each owns 32 gate columns
#define NBLK   (NW / MW)          // 128
#define KEXT   192                // 128 h + 50 emb + 1 bias + 13 pad
#define KATOMS (KEXT / 16)        // 12
#define ROWB   400                // smem row stride bytes (200 halves)

// ---- smem layout (round-5/9 proven) ----
#define SM_CI    0                          // 32*16*4 = 2048
#define SM_WIDX  2048                       // 32*4 = 128
#define SM_A     2176                       // 32*400 = 12800
#define SM_B     (SM_A + MW * ROWB)         // 14976; 512*400 = 204800
#define SM_TOTAL (SM_B + G4 * ROWB)         // 219776

// ---- device scratch ----
__device__ __align__(16) __half g_Bext[G4 * KEXT];  // permuted fused weights
__device__ __align__(16) __half g_embq[CV * 64];    // [emb(50) | 1 | 0pad] per char
__device__ float g_gsum[GD];
__device__ float g_hsum[CH];
__device__ float g_out2[2];
__device__ int   g_t2 = 0;

// ---- helpers ----
__device__ __forceinline__ uint32_t smem_u32(const void* p) {
    uint32_t a;
    asm("{ .reg .u64 t; cvta.to.shared.u64 t, %1; cvt.u32.u64 %0, t; }" : "=r"(a) : "l"(p));
    return a;
}
__device__ __forceinline__ void ldsm4(uint32_t addr, uint32_t r[4]) {
    asm volatile("ldmatrix.sync.aligned.m8n8.x4.shared.b16 {%0,%1,%2,%3}, [%4];"
        : "=r"(r[0]), "=r"(r[1]), "=r"(r[2]), "=r"(r[3]) : "r"(addr));
}
__device__ __forceinline__ void mma16816(float d[4], const uint32_t a[4], const uint32_t b[2]) {
    asm volatile("mma.sync.aligned.m16n8k16.row.col.f32.f16.f16.f32 "
        "{%0,%1,%2,%3}, {%4,%5,%6,%7}, {%8,%9}, {%0,%1,%2,%3};"
        : "+f"(d[0]), "+f"(d[1]), "+f"(d[2]), "+f"(d[3])
        : "r"(a[0]), "r"(a[1]), "r"(a[2]), "r"(a[3]), "r"(b[0]), "r"(b[1]));
}
__device__ __forceinline__ float tanha(float x) {
    float y; asm("tanh.approx.f32 %0, %1;" : "=f"(y) : "f"(x)); return y;
}
__device__ __forceinline__ float ldcv(const float* p) {
    float v; asm volatile("ld.global.cv.f32 %0, [%1];" : "=f"(v) : "l"(p)); return v;
}

// gate-column permutation: warp w owns cols j = w*32 + c, c = a*8 + q*2 + e
//   gate g = 2*(a>>1) + e ; unit u = w*8 + (a&1)*4 + q

// ---------------------------------------------------------------------------
// Prep: blocks 0..23 build g_Bext (8 halves per thread, float4 loads);
// block 24: embq + zero accumulators. grid 25 x 512
// ---------------------------------------------------------------------------
__global__ void prep_all(const float* __restrict__ W_hh, const float* __restrict__ W_ih,
                         const float* __restrict__ b_ih, const float* __restrict__ b_hh,
                         const float* __restrict__ char_embed) {
    if (blockIdx.x < 24) {
        int i = blockIdx.x * 512 + threadIdx.x;   // 0..12287 = 512 rows * 24 segs
        int j = i / 24, seg = i % 24;
        int ww = j >> 5, c = j & 31;
        int a = c >> 3, qq = (c >> 1) & 3, e = c & 1;
        int g = 2 * (a >> 1) + e;
        int u = ww * 8 + (a & 1) * 4 + qq;
        int row = g * CH + u;
        int k0 = seg * 8;
        __half2 h2v[4];
        if (seg < 16) {                           // W_hh: two coalesced float4
            float4 v0 = *(const float4*)(W_hh + row * CH + k0);
            float4 v1 = *(const float4*)(W_hh + row * CH + k0 + 4);
            h2v[0] = __floats2half2_rn(v0.x, v0.y);
            h2v[1] = __floats2half2_rn(v0.z, v0.w);
            h2v[2] = __floats2half2_rn(v1.x, v1.y);
            h2v[3] = __floats2half2_rn(v1.z, v1.w);
        } else {                                  // ext: W_ih | bias | pad
            float v[8];
#pragma unroll
            for (int d = 0; d < 8; d++) {
                int k = k0 + d;
                float x;
                if (k < CH + CE)       x = W_ih[row * CE + (k - CH)];
                else if (k == CH + CE) x = b_ih[row] + b_hh[row];
                else                   x = 0.f;
                v[d] = x;
            }
#pragma unroll
            for (int d = 0; d < 4; d++) h2v[d] = __floats2half2_rn(v[2 * d], v[2 * d + 1]);
        }
        *(uint4*)((unsigned char*)g_Bext + (j * KEXT + k0) * 2) = *(uint4*)h2v;
    } else {
        int tid = threadIdx.x;
        for (int idx = tid; idx < CV * 64; idx += 512) {
            int cix = idx >> 6, k = idx & 63;
            float v = (k < CE) ? char_embed[cix * CE + k] : (k == CE ? 1.f : 0.f);
            g_embq[idx] = __float2half(v);
        }
        if (tid < GD) g_gsum[tid] = 0.f;
        if (tid < CH) g_hsum[tid] = 0.f;
        if (tid == 0) { g_out2[0] = 0.f; g_out2[1] = 0.f; g_t2 = 0; }
    }
}

// ---------------------------------------------------------------------------
// LSTM via mma.sync + fused glove gather (round-9 structure; new epilogue)
// 128 CTAs x 512 thr; M=32 words, N=512 gates, K=192. B_ext smem-resident.
// ---------------------------------------------------------------------------
__global__ void __launch_bounds__(THR, 1) lstm_mma_kernel(const int* __restrict__ cidx,
                                                          const int* __restrict__ widx,
                                                          const float* __restrict__ glove) {
    extern __shared__ unsigned char sm[];
    uint32_t smb = smem_u32(sm);
    int tid = threadIdx.x;
    int w = tid >> 5, lane = tid & 31;
    int q = lane & 3, r = lane >> 2;

    const int wb = blockIdx.x * MW;
    for (int i = tid; i < MW * WLEN; i += THR)
        ((int*)(sm + SM_CI))[i] = cidx[wb * WLEN + i];
    if (tid < MW) ((int*)(sm + SM_WIDX))[tid] = widx[wb + tid];
    for (int i = tid; i < MW * ROWB / 16; i += THR)
        ((uint4*)(sm + SM_A))[i] = make_uint4(0, 0, 0, 0);
    for (int i = tid; i < G4 * 24; i += THR) {        // 24 uint4 per 192-half row
        int row = i / 24, s = i % 24;
        *(uint4*)(sm + SM_B + row * ROWB + s * 16) =
            *(const uint4*)((const unsigned char*)g_Bext + i * 16);
    }
    __syncthreads();

    // stage emb for t=0
    if (tid < 256) {
        int word = tid >> 3, seg = tid & 7;
        int ch = ((const int*)(sm + SM_CI))[word * WLEN];
        *(uint4*)(sm + SM_A + word * ROWB + 256 + seg * 16) =
            *(const uint4*)((const unsigned char*)g_embq + ch * 128 + seg * 16);
    }
    // fused glove column-sum for this CTA's 32 words
    if (tid < GD) {
        const int* rows = (const int*)(sm + SM_WIDX);
        float s = 0.f;
#pragma unroll
        for (int ww = 0; ww < MW; ww++)
            s += glove[(long long)rows[ww] * GD + tid];
        atomicAdd(&g_gsum[tid], s);
    }
    __syncthreads();

    // ldmatrix base addresses (loop-invariant)
    uint32_t aBase = smb + SM_A + (lane & 15) * ROWB + (lane >> 4) * 16;
    uint32_t bBase = smb + SM_B + (w * 32 + (lane >> 4) * 8 + (lane & 7)) * ROWB
                   + ((lane >> 3) & 1) * 16;

    float cst[8], hs0 = 0.f, hs1 = 0.f;
#pragma unroll
    for (int i = 0; i < 8; i++) cst[i] = 0.f;

#pragma unroll 1
    for (int t = 0; t < WLEN; t++) {
        float acc[2][4][4];
#pragma unroll
        for (int m2 = 0; m2 < 2; m2++)
#pragma unroll
            for (int n = 0; n < 4; n++)
#pragma unroll
                for (int x = 0; x < 4; x++) acc[m2][n][x] = 0.f;

#pragma unroll
        for (int ka = 0; ka < KATOMS; ka++) {
            uint32_t af[2][4], bf[2][4];
            ldsm4(aBase + ka * 32, af[0]);
            ldsm4(aBase + 16 * ROWB + ka * 32, af[1]);
            ldsm4(bBase + ka * 32, bf[0]);
            ldsm4(bBase + 16 * ROWB + ka * 32, bf[1]);
#pragma unroll
            for (int m2 = 0; m2 < 2; m2++)
#pragma unroll
                for (int n = 0; n < 4; n++)
                    mma16816(acc[m2][n], af[m2], &bf[n >> 1][(n & 1) * 2]);
        }

        // epilogue compute (registers only): 5 MUFU/unit via tanh.approx
        float hreg[8];
#pragma unroll
        for (int m2 = 0; m2 < 2; m2++)
#pragma unroll
            for (int h2 = 0; h2 < 2; h2++)
#pragma unroll
                for (int al = 0; al < 2; al++) {
                    float iv = acc[m2][al][h2 * 2];
                    float fv = acc[m2][al][h2 * 2 + 1];
                    float gv = acc[m2][al + 2][h2 * 2];
                    float ov = acc[m2][al + 2][h2 * 2 + 1];
                    int ci = (m2 * 2 + h2) * 2 + al;
                    float ii = fmaf(tanha(0.5f * iv), 0.5f, 0.5f);
                    float ff = fmaf(tanha(0.5f * fv), 0.5f, 0.5f);
                    float gg = tanha(gv);
                    float oo = fmaf(tanha(0.5f * ov), 0.5f, 0.5f);
                    float cn = fmaf(ff, cst[ci], ii * gg);
                    cst[ci] = cn;
                    hreg[ci] = oo * tanha(cn);
                }
        __syncthreads();   // all ldsm A-reads done before h/emb overwrite

#pragma unroll
        for (int m2 = 0; m2 < 2; m2++)
#pragma unroll
            for (int h2 = 0; h2 < 2; h2++)
#pragma unroll
                for (int al = 0; al < 2; al++) {
                    int ci = (m2 * 2 + h2) * 2 + al;
                    int m = m2 * 16 + r + h2 * 8;
                    int u = w * 8 + al * 4 + q;
                    *(__half*)(sm + SM_A + m * ROWB + u * 2) = __float2half(hreg[ci]);
                }
        if (t == WLEN - 1) {
#pragma unroll
            for (int ci = 0; ci < 8; ci++) {
                if ((ci & 1) == 0) hs0 += hreg[ci]; else hs1 += hreg[ci];
            }
        } else if (tid < 256) {   // stage emb for t+1
            int word = tid >> 3, seg = tid & 7;
            int ch = ((const int*)(sm + SM_CI))[word * WLEN + t + 1];
            *(uint4*)(sm + SM_A + word * ROWB + 256 + seg * 16) =
                *(const uint4*)((const unsigned char*)g_embq + ch * 128 + seg * 16);
        }
        __syncthreads();   // h + emb visible for next step
    }

    // reduce final h over the CTA's 32 words -> g_hsum
#pragma unroll
    for (int off = 4; off < 32; off <<= 1) {
        hs0 += __shfl_xor_sync(0xffffffffu, hs0, off);
        hs1 += __shfl_xor_sync(0xffffffffu, hs1, off);
    }
    if (lane < 4) {
        atomicAdd(&g_hsum[w * 8 + lane], hs0);
        atomicAdd(&g_hsum[w * 8 + 4 + lane], hs1);
    }
}

// ---------------------------------------------------------------------------
// Final: avg -> fc1 + relu -> fc2, parallelized over 8 CTAs (round-9 proven).
// ---------------------------------------------------------------------------
__global__ void final_kernel(const float* __restrict__ fc1_w,
                             const float* __restrict__ fc1_b,
                             const float* __restrict__ fc2_w,
                             const float* __restrict__ fc2_b,
                             float* __restrict__ out) {
    __shared__ float avg[FEAT];
    int tid = threadIdx.x;
    int lane = tid & 31;
    int e = tid & 7;                       // chunk within unit
    int j = blockIdx.x * 64 + (tid >> 3);  // hidden unit

    if (tid < GD) avg[tid] = g_gsum[tid] * (1.f / NW);
    else if (tid < FEAT) avg[tid] = g_hsum[tid - GD] * (1.f / NW);
    __syncthreads();

    int k0 = e * 54;
    int k1 = (k0 + 54 < FEAT) ? k0 + 54 : FEAT;
    const float* wrow = fc1_w + (long long)j * FEAT;
    float p = 0.f;
#pragma unroll 6
    for (int k = k0; k < k1; k++) p = fmaf(wrow[k], avg[k], p);
    p += __shfl_down_sync(0xffffffffu, p, 4, 8);
    p += __shfl_down_sync(0xffffffffu, p, 2, 8);
    p += __shfl_down_sync(0xffffffffu, p, 1, 8);

    float q0 = 0.f, q1 = 0.f;
    if (e == 0) {
        float h = fmaxf(p + fc1_b[j], 0.f);
        q0 = fc2_w[j] * h;
        q1 = fc2_w[HID + j] * h;
    }
#pragma unroll
    for (int off = 16; off >= 8; off >>= 1) {
        q0 += __shfl_down_sync(0xffffffffu, q0, off);
        q1 += __shfl_down_sync(0xffffffffu, q1, off);
    }
    if (lane == 0) {
        atomicAdd(&g_out2[0], q0);
        atomicAdd(&g_out2[1], q1);
    }
    __threadfence();
    __syncthreads();
    if (tid == 0) {
        int old = atomicAdd(&g_t2, 1);
        if (old == 7) {
            out[0] = ldcv(&g_out2[0]) + fc2_b[0];
            out[1] = ldcv(&g_out2[1]) + fc2_b[1];
        }
    }
}

// ---------------------------------------------------------------------------
extern "C" void kernel_launch(void* const* d_in, const int* in_sizes, int n_in,
                              void* d_out, int out_size) {
    const int*   widx  = (const int*)d_in[0];
    const int*   cidx  = (const int*)d_in[1];
    const float* glove = (const float*)d_in[2];
    const float* cemb  = (const float*)d_in[3];
    const float* W_ih  = (const float*)d_in[4];
    const float* W_hh  = (const float*)d_in[5];
    const float* b_ih  = (const float*)d_in[6];
    const float* b_hh  = (const float*)d_in[7];
    const float* fc1_w = (const float*)d_in[8];
    const float* fc1_b = (const float*)d_in[9];
    const float* fc2_w = (const float*)d_in[10];
    const float* fc2_b = (const float*)d_in[11];
    float* out = (float*)d_out;

    cudaFuncSetAttribute(lstm_mma_kernel,
                         cudaFuncAttributeMaxDynamicSharedMemorySize, SM_TOTAL);

    prep_all<<<25, 512>>>(W_hh, W_ih, b_ih, b_hh, cemb);
    lstm_mma_kernel<<<NBLK, THR, SM_TOTAL>>>(cidx, widx, glove);
    final_kernel<<<8, 512>>>(fc1_w, fc1_b, fc2_w, fc2_b, out);
}

// round 11
// speedup vs baseline: 2.3571x; 1.0667x over previous
#include <cuda_runtime.h>
#include <cuda_fp16.h>
#include <math.h>
#include <stdint.h>

#define NW     4096
#define WLEN   16
#define GD     300
#define CE     50
#define CH     128
#define G4     512
#define CV     100
#define HID    512
#define FEAT   428

#define MW     32                 // words per CTA (MMA M)
#define THR    512                // 16 warps, each owns 32 gate columns
#define NBLK   (NW / MW)          // 128
#define KEXT   192                // 128 h + 50 emb + 1 bias + 13 pad
#define KATOMS (KEXT / 16)        // 12
#define ROWB   400                // smem row stride bytes (200 halves)
#define ABYTES (MW * ROWB)        // 12800

// ---- smem layout (double-buffered A; total 231040, no static shared) ----
#define SM_CI8   0                          // 32*16 u8 = 512
#define SM_WIDX  512                        // 32*4 = 128
#define SM_A0    640                        // 12800
#define SM_A1    (SM_A0 + ABYTES)           // 13440
#define SM_B     (SM_A1 + ABYTES)           // 26240; 512*400 = 204800
#define SM_TOTAL (SM_B + G4 * ROWB)         // 231040

// ---- device scratch ----
__device__ __align__(16) __half g_Bext[G4 * KEXT];  // permuted fused weights
__device__ __align__(16) __half g_embq[CV * 64];    // [emb(50) | 1 | 0pad] per char
__device__ float g_gsum[GD];
__device__ float g_hsum[CH];
__device__ float g_out2[2];
__device__ int   g_t2 = 0;

// ---- helpers ----
__device__ __forceinline__ uint32_t smem_u32(const void* p) {
    uint32_t a;
    asm("{ .reg .u64 t; cvta.to.shared.u64 t, %1; cvt.u32.u64 %0, t; }" : "=r"(a) : "l"(p));
    return a;
}
__device__ __forceinline__ void ldsm4(uint32_t addr, uint32_t r[4]) {
    asm volatile("ldmatrix.sync.aligned.m8n8.x4.shared.b16 {%0,%1,%2,%3}, [%4];"
        : "=r"(r[0]), "=r"(r[1]), "=r"(r[2]), "=r"(r[3]) : "r"(addr));
}
__device__ __forceinline__ void mma16816(float d[4], const uint32_t a[4], const uint32_t b[2]) {
    asm volatile("mma.sync.aligned.m16n8k16.row.col.f32.f16.f16.f32 "
        "{%0,%1,%2,%3}, {%4,%5,%6,%7}, {%8,%9}, {%0,%1,%2,%3};"
        : "+f"(d[0]), "+f"(d[1]), "+f"(d[2]), "+f"(d[3])
        : "r"(a[0]), "r"(a[1]), "r"(a[2]), "r"(a[3]), "r"(b[0]), "r"(b[1]));
}
__device__ __forceinline__ float tanha(float x) {
    float y; asm("tanh.approx.f32 %0, %1;" : "=f"(y) : "f"(x)); return y;
}
__device__ __forceinline__ float ldcv(const float* p) {
    float v; asm volatile("ld.global.cv.f32 %0, [%1];" : "=f"(v) : "l"(p)); return v;
}

// gate-column permutation: warp w owns cols j = w*32 + c, c = a*8 + q*2 + e
//   gate g = 2*(a>>1) + e ; unit u = w*8 + (a&1)*4 + q

// ---------------------------------------------------------------------------
// Prep (round-9 proven, 4.7us): blocks 0..511 build g_Bext; 512..611 embq+zeros.
// grid 612 x 96
// ---------------------------------------------------------------------------
__global__ void prep_all(const float* __restrict__ W_hh, const float* __restrict__ W_ih,
                         const float* __restrict__ b_ih, const float* __restrict__ b_hh,
                         const float* __restrict__ char_embed) {
    if (blockIdx.x < G4) {
        int j = blockIdx.x;
        int w = j >> 5, c = j & 31;
        int a = c >> 3, q = (c >> 1) & 3, e = c & 1;
        int g = 2 * (a >> 1) + e;
        int u = w * 8 + (a & 1) * 4 + q;
        int row = g * CH + u;
        int k0 = threadIdx.x * 2;
        float v[2];
#pragma unroll
        for (int d = 0; d < 2; d++) {
            int k = k0 + d;
            float x;
            if (k < CH)            x = W_hh[row * CH + k];
            else if (k < CH + CE)  x = W_ih[row * CE + (k - CH)];
            else if (k == CH + CE) x = b_ih[row] + b_hh[row];
            else                   x = 0.f;
            v[d] = x;
        }
        *(__half2*)(g_Bext + j * KEXT + k0) = __floats2half2_rn(v[0], v[1]);
    } else {
        int cix = blockIdx.x - G4;
        int k = threadIdx.x;
        if (k < 64) {
            float v = (k < CE) ? char_embed[cix * CE + k] : (k == CE ? 1.f : 0.f);
            g_embq[cix * 64 + k] = __float2half(v);
        }
        int z = cix * 96 + threadIdx.x;
        if (z < GD) g_gsum[z] = 0.f;
        if (z < CH) g_hsum[z] = 0.f;
        if (blockIdx.x == G4 && threadIdx.x == 0) {
            g_out2[0] = 0.f; g_out2[1] = 0.f; g_t2 = 0;
        }
    }
}

// ---------------------------------------------------------------------------
// LSTM via mma.sync + fused glove gather; double-buffered A, 1 barrier/step.
// 128 CTAs x 512 thr; M=32 words, N=512 gates, K=192. B_ext smem-resident.
// ---------------------------------------------------------------------------
__global__ void __launch_bounds__(THR, 1) lstm_mma_kernel(const int* __restrict__ cidx,
                                                          const int* __restrict__ widx,
                                                          const float* __restrict__ glove) {
    extern __shared__ unsigned char sm[];
    uint32_t smb = smem_u32(sm);
    int tid = threadIdx.x;
    int w = tid >> 5, lane = tid & 31;
    int q = lane & 3, r = lane >> 2;

    const int wb = blockIdx.x * MW;
    if (tid < MW * WLEN) sm[SM_CI8 + tid] = (unsigned char)cidx[wb * WLEN + tid];
    if (tid < MW) ((int*)(sm + SM_WIDX))[tid] = widx[wb + tid];
    {   // zero A0 h-region (one uint4 per thread: 32 rows x 16 segs)
        int row = tid >> 4, seg = tid & 15;
        *(uint4*)(sm + SM_A0 + row * ROWB + seg * 16) = make_uint4(0, 0, 0, 0);
    }
    for (int i = tid; i < G4 * 24; i += THR) {        // 24 uint4 per 192-half row
        int row = i / 24, s = i % 24;
        *(uint4*)(sm + SM_B + row * ROWB + s * 16) =
            *(const uint4*)((const unsigned char*)g_Bext + i * 16);
    }
    __syncthreads();

    // stage emb for t=0 into A0
    if (tid < 256) {
        int word = tid >> 3, seg = tid & 7;
        int ch = sm[SM_CI8 + word * WLEN];
        *(uint4*)(sm + SM_A0 + word * ROWB + 256 + seg * 16) =
            *(const uint4*)((const unsigned char*)g_embq + ch * 128 + seg * 16);
    }
    // fused glove column-sum for this CTA's 32 words
    if (tid < GD) {
        const int* rows = (const int*)(sm + SM_WIDX);
        float s = 0.f;
#pragma unroll
        for (int ww = 0; ww < MW; ww++)
            s += glove[(long long)rows[ww] * GD + tid];
        atomicAdd(&g_gsum[tid], s);
    }
    __syncthreads();

    const uint32_t aoff = (uint32_t)((lane & 15) * ROWB + (lane >> 4) * 16);
    const uint32_t bBase = smb + SM_B + (w * 32 + (lane >> 4) * 8 + (lane & 7)) * ROWB
                         + ((lane >> 3) & 1) * 16;

    float cst[8], hs0 = 0.f, hs1 = 0.f;
#pragma unroll
    for (int i = 0; i < 8; i++) cst[i] = 0.f;

#pragma unroll 1
    for (int t = 0; t < WLEN; t++) {
        const uint32_t aBase = smb + SM_A0 + (t & 1) * ABYTES + aoff;
        const uint32_t aNxt = SM_A0 + ((t & 1) ^ 1) * ABYTES;

        float acc[2][4][4];
#pragma unroll
        for (int m2 = 0; m2 < 2; m2++)
#pragma unroll
            for (int n = 0; n < 4; n++)
#pragma unroll
                for (int x = 0; x < 4; x++) acc[m2][n][x] = 0.f;

#pragma unroll
        for (int ka = 0; ka < KATOMS; ka++) {
            uint32_t af[2][4], bf[2][4];
            ldsm4(aBase + ka * 32, af[0]);
            ldsm4(aBase + 16 * ROWB + ka * 32, af[1]);
            ldsm4(bBase + ka * 32, bf[0]);
            ldsm4(bBase + 16 * ROWB + ka * 32, bf[1]);
#pragma unroll
            for (int m2 = 0; m2 < 2; m2++)
#pragma unroll
                for (int n = 0; n < 4; n++)
                    mma16816(acc[m2][n], af[m2], &bf[n >> 1][(n & 1) * 2]);
        }

        // epilogue (registers) + h stores straight into the OTHER buffer —
        // step t-1's closing barrier already guarantees nobody still reads it
#pragma unroll
        for (int m2 = 0; m2 < 2; m2++)
#pragma unroll
            for (int h2 = 0; h2 < 2; h2++)
#pragma unroll
                for (int al = 0; al < 2; al++) {
                    float iv = acc[m2][al][h2 * 2];
                    float fv = acc[m2][al][h2 * 2 + 1];
                    float gv = acc[m2][al + 2][h2 * 2];
                    float ov = acc[m2][al + 2][h2 * 2 + 1];
                    int ci = (m2 * 2 + h2) * 2 + al;
                    float ii = fmaf(tanha(0.5f * iv), 0.5f, 0.5f);
                    float ff = fmaf(tanha(0.5f * fv), 0.5f, 0.5f);
                    float gg = tanha(gv);
                    float oo = fmaf(tanha(0.5f * ov), 0.5f, 0.5f);
                    float cn = fmaf(ff, cst[ci], ii * gg);
                    cst[ci] = cn;
                    float hv = oo * tanha(cn);
                    int m = m2 * 16 + r + h2 * 8;
                    int u = w * 8 + al * 4 + q;
                    *(__half*)(sm + aNxt + m * ROWB + u * 2) = __float2half(hv);
                    if (t == WLEN - 1) { if (al == 0) hs0 += hv; else hs1 += hv; }
                }

        if (t < WLEN - 1 && tid < 256) {   // stage emb for t+1 into A[next]
            int word = tid >> 3, seg = tid & 7;
            int ch = sm[SM_CI8 + word * WLEN + t + 1];
            *(uint4*)(sm + aNxt + word * ROWB + 256 + seg * 16) =
                *(const uint4*)((const unsigned char*)g_embq + ch * 128 + seg * 16);
        }
        __syncthreads();   // single barrier: RAW for next step + WAR for t+1 writes
    }

    // reduce final h over the CTA's 32 words -> g_hsum
#pragma unroll
    for (int off = 4; off < 32; off <<= 1) {
        hs0 += __shfl_xor_sync(0xffffffffu, hs0, off);
        hs1 += __shfl_xor_sync(0xffffffffu, hs1, off);
    }
    if (lane < 4) {
        atomicAdd(&g_hsum[w * 8 + lane], hs0);
        atomicAdd(&g_hsum[w * 8 + 4 + lane], hs1);
    }
}

// ---------------------------------------------------------------------------
// Final: avg -> fc1 + relu -> fc2, parallelized over 8 CTAs (round-9 proven).
// ---------------------------------------------------------------------------
__global__ void final_kernel(const float* __restrict__ fc1_w,
                             const float* __restrict__ fc1_b,
                             const float* __restrict__ fc2_w,
                             const float* __restrict__ fc2_b,
                             float* __restrict__ out) {
    __shared__ float avg[FEAT];
    int tid = threadIdx.x;
    int lane = tid & 31;
    int e = tid & 7;                       // chunk within unit
    int j = blockIdx.x * 64 + (tid >> 3);  // hidden unit

    if (tid < GD) avg[tid] = g_gsum[tid] * (1.f / NW);
    else if (tid < FEAT) avg[tid] = g_hsum[tid - GD] * (1.f / NW);
    __syncthreads();

    int k0 = e * 54;
    int k1 = (k0 + 54 < FEAT) ? k0 + 54 : FEAT;
    const float* wrow = fc1_w + (long long)j * FEAT;
    float p = 0.f;
#pragma unroll 6
    for (int k = k0; k < k1; k++) p = fmaf(wrow[k], avg[k], p);
    p += __shfl_down_sync(0xffffffffu, p, 4, 8);
    p += __shfl_down_sync(0xffffffffu, p, 2, 8);
    p += __shfl_down_sync(0xffffffffu, p, 1, 8);

    float q0 = 0.f, q1 = 0.f;
    if (e == 0) {
        float h = fmaxf(p + fc1_b[j], 0.f);
        q0 = fc2_w[j] * h;
        q1 = fc2_w[HID + j] * h;
    }
#pragma unroll
    for (int off = 16; off >= 8; off >>= 1) {
        q0 += __shfl_down_sync(0xffffffffu, q0, off);
        q1 += __shfl_down_sync(0xffffffffu, q1, off);
    }
    if (lane == 0) {
        atomicAdd(&g_out2[0], q0);
        atomicAdd(&g_out2[1], q1);
    }
    __threadfence();
    __syncthreads();
    if (tid == 0) {
        int old = atomicAdd(&g_t2, 1);
        if (old == 7) {
            out[0] = ldcv(&g_out2[0]) + fc2_b[0];
            out[1] = ldcv(&g_out2[1]) + fc2_b[1];
        }
    }
}

// ---------------------------------------------------------------------------
extern "C" void kernel_launch(void* const* d_in, const int* in_sizes, int n_in,
                              void* d_out, int out_size) {
    const int*   widx  = (const int*)d_in[0];
    const int*   cidx  = (const int*)d_in[1];
    const float* glove = (const float*)d_in[2];
    const float* cemb  = (const float*)d_in[3];
    const float* W_ih  = (const float*)d_in[4];
    const float* W_hh  = (const float*)d_in[5];
    const float* b_ih  = (const float*)d_in[6];
    const float* b_hh  = (const float*)d_in[7];
    const float* fc1_w = (const float*)d_in[8];
    const float* fc1_b = (const float*)d_in[9];
    const float* fc2_w = (const float*)d_in[10];
    const float* fc2_b = (const float*)d_in[11];
    float* out = (float*)d_out;

    cudaFuncSetAttribute(lstm_mma_kernel,
                         cudaFuncAttributeMaxDynamicSharedMemorySize, SM_TOTAL);

    prep_all<<<G4 + CV, 96>>>(W_hh, W_ih, b_ih, b_hh, cemb);
    lstm_mma_kernel<<<NBLK, THR, SM_TOTAL>>>(cidx, widx, glove);
    final_kernel<<<8, 512>>>(fc1_w, fc1_b, fc2_w, fc2_b, out);
}